// round 5
// baseline (speedup 1.0000x reference)
#include <cuda_runtime.h>
#include <cstdint>
#include <math.h>

// ---------------- problem constants ----------------
#define N_TOK 8192
#define DIM   1024
#define HID   2048
#define OUTD  1024
#define NEXP  8
#define TOPK  2
#define EPSBN 1e-5f

// ---------------- GEMM tiling ----------------
#define BM 128
#define BN 256
#define BKC 32               // K elements per pipeline stage
#define NSTAGE 3

#define ROWS_MAX (N_TOK*TOPK + NEXP*BM)   // 17408

#define APAD    36
#define A_STG_F (128*APAD)              // 4608
#define B_STG_F (256*APAD)              // 9216
#define STAGE_F (A_STG_F + B_STG_F)     // 13824 floats
#define PAR_F   (NSTAGE*STAGE_F)        // 41472
#define SMEM_FLOATS (PAR_F + 3*256)
#define SMEM_BYTES  (SMEM_FLOATS*4)     // 168960 bytes

// ---------------- static device scratch ----------------
__device__ float g_bufA[(size_t)ROWS_MAX * HID];
__device__ float g_bufB[(size_t)ROWS_MAX * HID];
__device__ int   g_cnt[NEXP];
__device__ int   g_off[NEXP + 1];
__device__ int   g_fill[NEXP];
__device__ int   g_tok2[N_TOK * TOPK];
__device__ float g_w2[N_TOK * TOPK];
__device__ int   g_rowtok[ROWS_MAX];
__device__ float g_roww[ROWS_MAX];

// ---------------- helpers (family-agnostic sm_80+ PTX) ----------------
__device__ __forceinline__ uint32_t smem_u32(const void* p) {
    uint32_t a;
    asm("{ .reg .u64 t; cvta.to.shared.u64 t, %1; cvt.u32.u64 %0, t; }" : "=r"(a) : "l"(p));
    return a;
}
__device__ __forceinline__ void cp16(uint32_t dst, const void* src, int szbytes) {
    asm volatile("cp.async.cg.shared.global [%0], [%1], 16, %2;"
                 :: "r"(dst), "l"(src), "r"(szbytes) : "memory");
}
template<int N> __device__ __forceinline__ void cp_wait() {
    asm volatile("cp.async.wait_group %0;" :: "n"(N) : "memory");
}
__device__ __forceinline__ void cp_commit() {
    asm volatile("cp.async.commit_group;" ::: "memory");
}
__device__ __forceinline__ uint32_t f2tf(float f) {
    uint32_t r;
    asm("cvt.rna.tf32.f32 %0, %1;" : "=r"(r) : "f"(f));
    return r;
}
__device__ __forceinline__ void mma_tf32(float* c, const uint32_t* a, const uint32_t* b) {
    asm volatile("mma.sync.aligned.m16n8k8.row.col.f32.tf32.tf32.f32 "
                 "{%0,%1,%2,%3}, {%4,%5,%6,%7}, {%8,%9}, {%0,%1,%2,%3};"
                 : "+f"(c[0]), "+f"(c[1]), "+f"(c[2]), "+f"(c[3])
                 : "r"(a[0]), "r"(a[1]), "r"(a[2]), "r"(a[3]),
                   "r"(b[0]), "r"(b[1]));
}

// ---------------- routing kernels ----------------
__global__ void k_init() {
    int i = blockIdx.x * blockDim.x + threadIdx.x;
    if (i < ROWS_MAX) g_rowtok[i] = -1;
    if (i < NEXP)     g_cnt[i] = 0;
}

__global__ void k_gate(const float* __restrict__ x, const float* __restrict__ Wg) {
    int warp = threadIdx.x >> 5;
    int lane = threadIdx.x & 31;
    int t = blockIdx.x * 8 + warp;
    if (t >= N_TOK) return;
    const float* xr = x + (size_t)t * DIM;
    float acc[NEXP];
#pragma unroll
    for (int e = 0; e < NEXP; e++) acc[e] = 0.f;
    for (int d = lane; d < DIM; d += 32) {
        float xv = xr[d];
#pragma unroll
        for (int e = 0; e < NEXP; e++) acc[e] = fmaf(xv, Wg[e * DIM + d], acc[e]);
    }
#pragma unroll
    for (int e = 0; e < NEXP; e++)
#pragma unroll
        for (int s = 16; s > 0; s >>= 1) acc[e] += __shfl_xor_sync(0xffffffffu, acc[e], s);
    if (lane == 0) {
        float mx = acc[0];
#pragma unroll
        for (int e = 1; e < NEXP; e++) mx = fmaxf(mx, acc[e]);
        float p[NEXP], sum = 0.f;
#pragma unroll
        for (int e = 0; e < NEXP; e++) { p[e] = expf(acc[e] - mx); sum += p[e]; }
        float inv = 1.f / sum;
#pragma unroll
        for (int e = 0; e < NEXP; e++) p[e] *= inv;
        int i0 = 0;
#pragma unroll
        for (int e = 1; e < NEXP; e++) if (p[e] > p[i0]) i0 = e;
        int i1 = (i0 == 0) ? 1 : 0;
#pragma unroll
        for (int e = 0; e < NEXP; e++) if (e != i0 && p[e] > p[i1]) i1 = e;
        float den = p[i0] + p[i1] + 1e-20f;
        g_tok2[2 * t + 0] = i0; g_w2[2 * t + 0] = p[i0] / den;
        g_tok2[2 * t + 1] = i1; g_w2[2 * t + 1] = p[i1] / den;
        atomicAdd(&g_cnt[i0], 1);
        atomicAdd(&g_cnt[i1], 1);
    }
}

__global__ void k_offsets() {
    if (threadIdx.x == 0) {
        int o = 0;
        for (int e = 0; e < NEXP; e++) { g_off[e] = o; o += ((g_cnt[e] + BM - 1) / BM) * BM; }
        g_off[NEXP] = o;
    }
    if (threadIdx.x < NEXP) g_fill[threadIdx.x] = 0;
}

__global__ void k_scatter() {
    int t = blockIdx.x * blockDim.x + threadIdx.x;
    if (t >= N_TOK) return;
#pragma unroll
    for (int s = 0; s < TOPK; s++) {
        int e = g_tok2[2 * t + s];
        int pos = g_off[e] + atomicAdd(&g_fill[e], 1);
        g_rowtok[pos] = t;
        g_roww[pos]  = g_w2[2 * t + s];
    }
}

// ---------------- tf32 mma.sync fused GEMM ----------------
// CTA tile 128x256, 8 warps (2x4), warp tile 64x64.
// 3-stage cp.async pipeline, K-chunk 32, one __syncthreads per chunk.
// EPI 0: relu+BN store   EPI 1: sigmoid store   EPI 2: w*sigmoid atomicAdd scatter
template<int EPI, bool GATHER>
__global__ void __launch_bounds__(256, 1)
gemm_tc(const float* __restrict__ X,
        const float* __restrict__ Wb,
        const float* __restrict__ biasb,
        const float* __restrict__ gb, const float* __restrict__ beb,
        const float* __restrict__ mb, const float* __restrict__ vb,
        float* __restrict__ out,
        int Kd, int Hout,
        long wstride, int pstride,
        const int* __restrict__ off)
{
    extern __shared__ float smf[];
    int tid = threadIdx.x;
    int wid = tid >> 5;
    int lid = tid & 31;

    int tileStart = blockIdx.y * BM;
    int e = 0;
    if (off) {
        int total = off[NEXP];
        if (tileStart >= total) return;
        while (e < NEXP - 1 && off[e + 1] <= tileStart) e++;
    }
    const float* W    = Wb    + (size_t)e * (size_t)wstride;
    const float* bias = biasb + (size_t)e * (size_t)pstride;
    int nbase = blockIdx.x * BN;

    // epilogue params
    float* par_b  = smf + PAR_F;
    float* par_sc = par_b + 256;
    float* par_sh = par_b + 512;
    {
        int n = nbase + tid;
        par_b[tid] = bias[n];
        if (EPI == 0) {
            size_t pe = (size_t)e * (size_t)pstride + n;
            float s = gb[pe] * rsqrtf(vb[pe] + EPSBN);
            par_sc[tid] = s;
            par_sh[tid] = fmaf(-mb[pe], s, beb[pe]);
        }
    }

    // producer mapping: lrow 0..31, lcol = 4-float column
    int lrow = tid >> 3;            // 0..31
    int lcol = (tid & 7) * 4;       // 0,4,...,28
    const float* asrc[4]; int asz[4];
#pragma unroll
    for (int i = 0; i < 4; i++) {
        int r = lrow + 32 * i;
        if (GATHER) {
            int tok = g_rowtok[tileStart + r];
            asrc[i] = X + (size_t)(tok >= 0 ? tok : 0) * Kd + lcol;
            asz[i]  = tok >= 0 ? 16 : 0;
        } else {
            asrc[i] = X + (size_t)(tileStart + r) * Kd + lcol;
            asz[i]  = 16;
        }
    }
    const float* bbase = W + (size_t)(nbase + lrow) * Kd + lcol;

    uint32_t sb = smem_u32(smf);
    uint32_t adst = sb + (uint32_t)(lrow * APAD + lcol) * 4u;
    uint32_t bdst = sb + (uint32_t)((128 + lrow) * APAD + lcol) * 4u;

    float acc[32][4];
#pragma unroll
    for (int i = 0; i < 32; i++)
#pragma unroll
        for (int j = 0; j < 4; j++) acc[i][j] = 0.f;

    int warpM = wid & 1;           // 0..1 -> 64 rows
    int warpN = wid >> 1;          // 0..3 -> 64 cols
    int g = lid >> 2, t = lid & 3;

    int Nc = Kd / BKC;

    // prologue: stages 0,1
#pragma unroll
    for (int p = 0; p < 2; p++) {
        uint32_t so = (uint32_t)(p * STAGE_F) * 4u;
        int k0 = p * BKC;
#pragma unroll
        for (int i = 0; i < 4; i++)
            cp16(adst + so + (uint32_t)(32 * i * APAD) * 4u, asrc[i] + k0, asz[i]);
#pragma unroll
        for (int i = 0; i < 8; i++)
            cp16(bdst + so + (uint32_t)(32 * i * APAD) * 4u, bbase + (size_t)(32 * i) * Kd + k0, 16);
        cp_commit();
    }

    int stage = 0;
    for (int c = 0; c < Nc; c++) {
        if (c + 1 < Nc) cp_wait<1>(); else cp_wait<0>();
        __syncthreads();   // chunk c visible; all warps done computing chunk c-1

        if (c + 2 < Nc) {
            int sidx = (c + 2) % NSTAGE;
            uint32_t so = (uint32_t)(sidx * STAGE_F) * 4u;
            int k0 = (c + 2) * BKC;
#pragma unroll
            for (int i = 0; i < 4; i++)
                cp16(adst + so + (uint32_t)(32 * i * APAD) * 4u, asrc[i] + k0, asz[i]);
#pragma unroll
            for (int i = 0; i < 8; i++)
                cp16(bdst + so + (uint32_t)(32 * i * APAD) * 4u, bbase + (size_t)(32 * i) * Kd + k0, 16);
            cp_commit();
        }

        const float* As = smf + stage * STAGE_F;
        const float* Bs = As + A_STG_F;
#pragma unroll
        for (int ks = 0; ks < 4; ks++) {
            int ko = ks * 8;
            uint32_t a[4][4];
#pragma unroll
            for (int mt = 0; mt < 4; mt++) {
                int r = warpM * 64 + mt * 16 + g;
                a[mt][0] = f2tf(As[r * APAD + ko + t]);
                a[mt][1] = f2tf(As[(r + 8) * APAD + ko + t]);
                a[mt][2] = f2tf(As[r * APAD + ko + t + 4]);
                a[mt][3] = f2tf(As[(r + 8) * APAD + ko + t + 4]);
            }
            uint32_t b[8][2];
#pragma unroll
            for (int nt = 0; nt < 8; nt++) {
                int r = warpN * 64 + nt * 8 + g;
                b[nt][0] = f2tf(Bs[r * APAD + ko + t]);
                b[nt][1] = f2tf(Bs[r * APAD + ko + t + 4]);
            }
#pragma unroll
            for (int mt = 0; mt < 4; mt++)
#pragma unroll
                for (int nt = 0; nt < 8; nt++)
                    mma_tf32(acc[mt * 8 + nt], a[mt], b[nt]);
        }
        stage = (stage + 1 == NSTAGE) ? 0 : stage + 1;
    }

    // ---- epilogue ----
#pragma unroll
    for (int mt = 0; mt < 4; mt++) {
        int rl0 = warpM * 64 + mt * 16 + g;
        int r0 = tileStart + rl0;
        int r1 = r0 + 8;
        int tok0 = 0, tok1 = 0; float w0 = 0.f, w1 = 0.f;
        if (EPI == 2) {
            tok0 = g_rowtok[r0]; tok1 = g_rowtok[r1];
            w0 = g_roww[r0];     w1 = g_roww[r1];
        }
#pragma unroll
        for (int nt = 0; nt < 8; nt++) {
            float* c = acc[mt * 8 + nt];
            int colL = warpN * 64 + nt * 8 + 2 * t;
            int col = nbase + colL;
            if (EPI == 0) {
                float b0 = par_b[colL], b1 = par_b[colL + 1];
                float s0 = par_sc[colL], s1 = par_sc[colL + 1];
                float h0 = par_sh[colL], h1 = par_sh[colL + 1];
                float2 o0, o1;
                o0.x = fmaf(fmaxf(c[0] + b0, 0.f), s0, h0);
                o0.y = fmaf(fmaxf(c[1] + b1, 0.f), s1, h1);
                o1.x = fmaf(fmaxf(c[2] + b0, 0.f), s0, h0);
                o1.y = fmaf(fmaxf(c[3] + b1, 0.f), s1, h1);
                *(float2*)(out + (size_t)r0 * Hout + col) = o0;
                *(float2*)(out + (size_t)r1 * Hout + col) = o1;
            } else if (EPI == 1) {
                float b0 = par_b[colL], b1 = par_b[colL + 1];
                float2 o0, o1;
                o0.x = 1.f / (1.f + __expf(-(c[0] + b0)));
                o0.y = 1.f / (1.f + __expf(-(c[1] + b1)));
                o1.x = 1.f / (1.f + __expf(-(c[2] + b0)));
                o1.y = 1.f / (1.f + __expf(-(c[3] + b1)));
                *(float2*)(out + (size_t)r0 * Hout + col) = o0;
                *(float2*)(out + (size_t)r1 * Hout + col) = o1;
            } else {
                float b0 = par_b[colL], b1 = par_b[colL + 1];
                if (tok0 >= 0) {
                    float* orow = out + (size_t)tok0 * Hout + col;
                    atomicAdd(&orow[0], w0 * (1.f / (1.f + __expf(-(c[0] + b0)))));
                    atomicAdd(&orow[1], w0 * (1.f / (1.f + __expf(-(c[1] + b1)))));
                }
                if (tok1 >= 0) {
                    float* orow = out + (size_t)tok1 * Hout + col;
                    atomicAdd(&orow[0], w1 * (1.f / (1.f + __expf(-(c[2] + b0)))));
                    atomicAdd(&orow[1], w1 * (1.f / (1.f + __expf(-(c[3] + b1)))));
                }
            }
        }
    }
}

// ---------------- launch ----------------
extern "C" void kernel_launch(void* const* d_in, const int* in_sizes, int n_in,
                              void* d_out, int out_size) {
    (void)in_sizes; (void)n_in; (void)out_size;

    const float* x   = (const float*)d_in[0];
    const float* Wg  = (const float*)d_in[1];
    const float* W1  = (const float*)d_in[2];
    const float* b1  = (const float*)d_in[3];
    const float* g1  = (const float*)d_in[4];
    const float* be1 = (const float*)d_in[5];
    const float* m1  = (const float*)d_in[6];
    const float* v1  = (const float*)d_in[7];
    const float* W2  = (const float*)d_in[8];
    const float* b2  = (const float*)d_in[9];
    const float* g2  = (const float*)d_in[10];
    const float* be2 = (const float*)d_in[11];
    const float* m2  = (const float*)d_in[12];
    const float* v2  = (const float*)d_in[13];
    const float* W3  = (const float*)d_in[14];
    const float* b3  = (const float*)d_in[15];
    const float* sW1 = (const float*)d_in[16];
    const float* sb1 = (const float*)d_in[17];
    const float* sg1 = (const float*)d_in[18];
    const float* sbe1= (const float*)d_in[19];
    const float* sm1 = (const float*)d_in[20];
    const float* sv1 = (const float*)d_in[21];
    const float* sW2 = (const float*)d_in[22];
    const float* sb2 = (const float*)d_in[23];
    const float* sg2 = (const float*)d_in[24];
    const float* sbe2= (const float*)d_in[25];
    const float* sm2 = (const float*)d_in[26];
    const float* sv2 = (const float*)d_in[27];
    const float* sW3 = (const float*)d_in[28];
    const float* sb3 = (const float*)d_in[29];
    float* out = (float*)d_out;

    float* bufA; float* bufB; int* off;
    cudaGetSymbolAddress((void**)&bufA, g_bufA);
    cudaGetSymbolAddress((void**)&bufB, g_bufB);
    cudaGetSymbolAddress((void**)&off,  g_off);

    cudaFuncSetAttribute(gemm_tc<0, true>,  cudaFuncAttributeMaxDynamicSharedMemorySize, SMEM_BYTES);
    cudaFuncSetAttribute(gemm_tc<0, false>, cudaFuncAttributeMaxDynamicSharedMemorySize, SMEM_BYTES);
    cudaFuncSetAttribute(gemm_tc<1, false>, cudaFuncAttributeMaxDynamicSharedMemorySize, SMEM_BYTES);
    cudaFuncSetAttribute(gemm_tc<2, false>, cudaFuncAttributeMaxDynamicSharedMemorySize, SMEM_BYTES);

    // routing
    k_init<<<(ROWS_MAX + 255) / 256, 256>>>();
    k_gate<<<N_TOK / 8, 256>>>(x, Wg);
    k_offsets<<<1, 32>>>();
    k_scatter<<<(N_TOK + 255) / 256, 256>>>();

    // shared expert: x -> bufA -> bufB -> out (plain store initializes d_out)
    gemm_tc<0, false><<<dim3(HID / BN, N_TOK / BM), 256, SMEM_BYTES>>>(
        x, sW1, sb1, sg1, sbe1, sm1, sv1, bufA, DIM, HID, 0, 0, nullptr);
    gemm_tc<0, false><<<dim3(HID / BN, N_TOK / BM), 256, SMEM_BYTES>>>(
        bufA, sW2, sb2, sg2, sbe2, sm2, sv2, bufB, HID, HID, 0, 0, nullptr);
    gemm_tc<1, false><<<dim3(OUTD / BN, N_TOK / BM), 256, SMEM_BYTES>>>(
        bufB, sW3, sb3, nullptr, nullptr, nullptr, nullptr, out, HID, OUTD, 0, 0, nullptr);

    // routed experts (top-2 compacted): gather -> bufA -> bufB -> out (+=)
    gemm_tc<0, true><<<dim3(HID / BN, ROWS_MAX / BM), 256, SMEM_BYTES>>>(
        x, W1, b1, g1, be1, m1, v1, bufA, DIM, HID, (long)HID * DIM, HID, off);
    gemm_tc<0, false><<<dim3(HID / BN, ROWS_MAX / BM), 256, SMEM_BYTES>>>(
        bufA, W2, b2, g2, be2, m2, v2, bufB, HID, HID, (long)HID * HID, HID, off);
    gemm_tc<2, false><<<dim3(OUTD / BN, ROWS_MAX / BM), 256, SMEM_BYTES>>>(
        bufB, W3, b3, nullptr, nullptr, nullptr, nullptr, out, HID, OUTD, (long)OUTD * HID, OUTD, off);
}

// round 6
// speedup vs baseline: 2.2936x; 2.2936x over previous
#include <cuda_runtime.h>
#include <cuda_fp16.h>
#include <cstdint>
#include <math.h>

// ---------------- problem constants ----------------
#define N_TOK 8192
#define DIM   1024
#define HID   2048
#define OUTD  1024
#define NEXP  8
#define TOPK  2
#define EPSBN 1e-5f

// ---------------- GEMM tiling ----------------
#define BM 128
#define BN 128
#define BKC 64               // K elements per pipeline stage (fp16: 128B rows)
#define NSTAGE 3
#define PITCH 72             // smem row pitch in halves (144B, ldmatrix conflict-free)

#define ROWS_MAX (N_TOK*TOPK + NEXP*BM)   // 17408

#define A_STG_H (128*PITCH)              // 9216 halves
#define STAGE_H (2*A_STG_H)              // A+B per stage
#define PAR_OFF_B (NSTAGE*STAGE_H*2)     // 110592 bytes
#define SMEM_BYTES (PAR_OFF_B + 3*128*4) // 112128 bytes

// ---------------- static device scratch ----------------
__device__ __half g_x16[(size_t)N_TOK * DIM];
__device__ __half g_w1[(size_t)NEXP * HID * DIM];
__device__ __half g_w2[(size_t)NEXP * HID * HID];
__device__ __half g_w3[(size_t)NEXP * OUTD * HID];
__device__ __half g_sw1[(size_t)HID * DIM];
__device__ __half g_sw2[(size_t)HID * HID];
__device__ __half g_sw3[(size_t)OUTD * HID];
__device__ __half g_bufA[(size_t)ROWS_MAX * HID];
__device__ __half g_bufB[(size_t)ROWS_MAX * HID];
__device__ int   g_cnt[NEXP];
__device__ int   g_off[NEXP + 1];
__device__ int   g_fill[NEXP];
__device__ int   g_tok2[N_TOK * TOPK];
__device__ float g_w2g[N_TOK * TOPK];
__device__ int   g_rowtok[ROWS_MAX];
__device__ float g_roww[ROWS_MAX];

// ---------------- helpers (family-agnostic sm_80+ PTX) ----------------
__device__ __forceinline__ uint32_t smem_u32(const void* p) {
    uint32_t a;
    asm("{ .reg .u64 t; cvta.to.shared.u64 t, %1; cvt.u32.u64 %0, t; }" : "=r"(a) : "l"(p));
    return a;
}
__device__ __forceinline__ void cp16(uint32_t dst, const void* src, int szbytes) {
    asm volatile("cp.async.cg.shared.global [%0], [%1], 16, %2;"
                 :: "r"(dst), "l"(src), "r"(szbytes) : "memory");
}
template<int N> __device__ __forceinline__ void cp_wait() {
    asm volatile("cp.async.wait_group %0;" :: "n"(N) : "memory");
}
__device__ __forceinline__ void cp_commit() {
    asm volatile("cp.async.commit_group;" ::: "memory");
}
__device__ __forceinline__ void ldsm_x4(uint32_t addr, uint32_t* r) {
    asm volatile("ldmatrix.sync.aligned.m8n8.x4.shared.b16 {%0,%1,%2,%3}, [%4];"
                 : "=r"(r[0]), "=r"(r[1]), "=r"(r[2]), "=r"(r[3]) : "r"(addr));
}
__device__ __forceinline__ void mma_f16(float* c, const uint32_t* a, uint32_t b0, uint32_t b1) {
    asm volatile("mma.sync.aligned.m16n8k16.row.col.f32.f16.f16.f32 "
                 "{%0,%1,%2,%3}, {%4,%5,%6,%7}, {%8,%9}, {%0,%1,%2,%3};"
                 : "+f"(c[0]), "+f"(c[1]), "+f"(c[2]), "+f"(c[3])
                 : "r"(a[0]), "r"(a[1]), "r"(a[2]), "r"(a[3]), "r"(b0), "r"(b1));
}

// ---------------- routing kernels ----------------
__global__ void k_init() {
    int i = blockIdx.x * blockDim.x + threadIdx.x;
    if (i < ROWS_MAX) g_rowtok[i] = -1;
    if (i < NEXP)     g_cnt[i] = 0;
}

__global__ void k_gate(const float* __restrict__ x, const float* __restrict__ Wg) {
    int warp = threadIdx.x >> 5;
    int lane = threadIdx.x & 31;
    int t = blockIdx.x * 8 + warp;
    if (t >= N_TOK) return;
    const float* xr = x + (size_t)t * DIM;
    float acc[NEXP];
#pragma unroll
    for (int e = 0; e < NEXP; e++) acc[e] = 0.f;
    for (int d = lane; d < DIM; d += 32) {
        float xv = xr[d];
#pragma unroll
        for (int e = 0; e < NEXP; e++) acc[e] = fmaf(xv, Wg[e * DIM + d], acc[e]);
    }
#pragma unroll
    for (int e = 0; e < NEXP; e++)
#pragma unroll
        for (int s = 16; s > 0; s >>= 1) acc[e] += __shfl_xor_sync(0xffffffffu, acc[e], s);
    if (lane == 0) {
        float mx = acc[0];
#pragma unroll
        for (int e = 1; e < NEXP; e++) mx = fmaxf(mx, acc[e]);
        float p[NEXP], sum = 0.f;
#pragma unroll
        for (int e = 0; e < NEXP; e++) { p[e] = expf(acc[e] - mx); sum += p[e]; }
        float inv = 1.f / sum;
#pragma unroll
        for (int e = 0; e < NEXP; e++) p[e] *= inv;
        int i0 = 0;
#pragma unroll
        for (int e = 1; e < NEXP; e++) if (p[e] > p[i0]) i0 = e;
        int i1 = (i0 == 0) ? 1 : 0;
#pragma unroll
        for (int e = 0; e < NEXP; e++) if (e != i0 && p[e] > p[i1]) i1 = e;
        float den = p[i0] + p[i1] + 1e-20f;
        g_tok2[2 * t + 0] = i0; g_w2g[2 * t + 0] = p[i0] / den;
        g_tok2[2 * t + 1] = i1; g_w2g[2 * t + 1] = p[i1] / den;
        atomicAdd(&g_cnt[i0], 1);
        atomicAdd(&g_cnt[i1], 1);
    }
}

__global__ void k_offsets() {
    if (threadIdx.x == 0) {
        int o = 0;
        for (int e = 0; e < NEXP; e++) { g_off[e] = o; o += ((g_cnt[e] + BM - 1) / BM) * BM; }
        g_off[NEXP] = o;
    }
    if (threadIdx.x < NEXP) g_fill[threadIdx.x] = 0;
}

__global__ void k_scatter() {
    int t = blockIdx.x * blockDim.x + threadIdx.x;
    if (t >= N_TOK) return;
#pragma unroll
    for (int s = 0; s < TOPK; s++) {
        int e = g_tok2[2 * t + s];
        int pos = g_off[e] + atomicAdd(&g_fill[e], 1);
        g_rowtok[pos] = t;
        g_roww[pos]  = g_w2g[2 * t + s];
    }
}

// ---------------- fp32 -> fp16 conversion ----------------
__global__ void k_cvt(const float* __restrict__ s, __half* __restrict__ d, int n) {
    int i = (blockIdx.x * blockDim.x + threadIdx.x) * 4;
    if (i >= n) return;
    float4 v = *(const float4*)(s + i);
    *(__half2*)(d + i)     = __floats2half2_rn(v.x, v.y);
    *(__half2*)(d + i + 2) = __floats2half2_rn(v.z, v.w);
}

// ---------------- fp16 mma.sync fused GEMM ----------------
// CTA tile 128x128, 8 warps (2x4), warp tile 64x32, m16n8k16 f16->f32.
// 3-stage cp.async pipeline, K-chunk 64, ldmatrix fragment loads.
// EPI 0: relu+BN -> __half store   EPI 1: sigmoid -> f32 store
// EPI 2: w*sigmoid atomicAdd scatter -> f32
template<int EPI, bool GATHER>
__global__ void __launch_bounds__(256, 2)
gemm_h(const __half* __restrict__ X,
       const __half* __restrict__ Wb,
       const float* __restrict__ biasb,
       const float* __restrict__ gb, const float* __restrict__ beb,
       const float* __restrict__ mb, const float* __restrict__ vb,
       void* __restrict__ outv,
       int Kd, int Hout,
       long wstride, int pstride,
       const int* __restrict__ off)
{
    extern __shared__ char smc[];
    __half* sm = (__half*)smc;
    int tid = threadIdx.x;
    int wid = tid >> 5;
    int lid = tid & 31;

    int tileStart = blockIdx.y * BM;
    int e = 0;
    if (off) {
        int total = off[NEXP];
        if (tileStart >= total) return;
        while (e < NEXP - 1 && off[e + 1] <= tileStart) e++;
    }
    const __half* W   = Wb    + (size_t)e * (size_t)wstride;
    const float* bias = biasb + (size_t)e * (size_t)pstride;
    int nbase = blockIdx.x * BN;

    // epilogue params
    float* par_b  = (float*)(smc + PAR_OFF_B);
    float* par_sc = par_b + 128;
    float* par_sh = par_b + 256;
    if (tid < 128) {
        int n = nbase + tid;
        par_b[tid] = bias[n];
        if (EPI == 0) {
            size_t pe = (size_t)e * (size_t)pstride + n;
            float s = gb[pe] * rsqrtf(vb[pe] + EPSBN);
            par_sc[tid] = s;
            par_sh[tid] = fmaf(-mb[pe], s, beb[pe]);
        }
    }

    // producer mapping: 128 rows x 128B per matrix; 8 threads/row, 4 row-groups
    int lrow = tid >> 3;            // 0..31
    int lc   = (tid & 7) * 8;       // half offset (0..56)
    const __half* asrc[4]; int asz[4];
#pragma unroll
    for (int i = 0; i < 4; i++) {
        int r = lrow + 32 * i;
        if (GATHER) {
            int tok = g_rowtok[tileStart + r];
            asrc[i] = X + (size_t)(tok >= 0 ? tok : 0) * Kd + lc;
            asz[i]  = tok >= 0 ? 16 : 0;
        } else {
            asrc[i] = X + (size_t)(tileStart + r) * Kd + lc;
            asz[i]  = 16;
        }
    }
    const __half* bbase = W + (size_t)(nbase + lrow) * Kd + lc;

    uint32_t sb = smem_u32(sm);
    uint32_t adst = sb + (uint32_t)(lrow * PITCH + lc) * 2u;
    uint32_t bdst = adst + (uint32_t)A_STG_H * 2u;

    float acc[16][4];
#pragma unroll
    for (int i = 0; i < 16; i++)
#pragma unroll
        for (int j = 0; j < 4; j++) acc[i][j] = 0.f;

    int warpM = wid & 1;           // 0..1 -> 64 rows
    int warpN = wid >> 1;          // 0..3 -> 32 cols
    int g = lid >> 2, t = lid & 3;

    // ldmatrix lane address components
    int aRowSel = lid & 15;
    int aColSel = (lid >> 4) * 8;                      // halves
    int bNoff   = (lid & 7) + ((lid >> 4) << 3);
    int bKoff   = ((lid >> 3) & 1) * 8;

    int Nc = Kd / BKC;

    // prologue: stages 0,1
#pragma unroll
    for (int p = 0; p < 2; p++) {
        uint32_t so = (uint32_t)(p * STAGE_H) * 2u;
        int k0 = p * BKC;
#pragma unroll
        for (int i = 0; i < 4; i++) {
            cp16(adst + so + (uint32_t)(32 * i * PITCH) * 2u, asrc[i] + k0, asz[i]);
            cp16(bdst + so + (uint32_t)(32 * i * PITCH) * 2u, bbase + (size_t)(32 * i) * Kd + k0, 16);
        }
        cp_commit();
    }

    int stage = 0;
    for (int c = 0; c < Nc; c++) {
        if (c + 1 < Nc) cp_wait<1>(); else cp_wait<0>();
        __syncthreads();

        if (c + 2 < Nc) {
            int sidx = (c + 2) % NSTAGE;
            uint32_t so = (uint32_t)(sidx * STAGE_H) * 2u;
            int k0 = (c + 2) * BKC;
#pragma unroll
            for (int i = 0; i < 4; i++) {
                cp16(adst + so + (uint32_t)(32 * i * PITCH) * 2u, asrc[i] + k0, asz[i]);
                cp16(bdst + so + (uint32_t)(32 * i * PITCH) * 2u, bbase + (size_t)(32 * i) * Kd + k0, 16);
            }
            cp_commit();
        }

        uint32_t As = sb + (uint32_t)(stage * STAGE_H) * 2u;
        uint32_t Bs = As + (uint32_t)A_STG_H * 2u;
#pragma unroll
        for (int ks = 0; ks < 4; ks++) {
            uint32_t a[4][4];
#pragma unroll
            for (int mt = 0; mt < 4; mt++) {
                uint32_t addr = As + (uint32_t)((warpM * 64 + mt * 16 + aRowSel) * PITCH
                                                + ks * 16 + aColSel) * 2u;
                ldsm_x4(addr, a[mt]);
            }
            uint32_t b[2][4];
#pragma unroll
            for (int ntp = 0; ntp < 2; ntp++) {
                uint32_t addr = Bs + (uint32_t)((warpN * 32 + ntp * 16 + bNoff) * PITCH
                                                + ks * 16 + bKoff) * 2u;
                ldsm_x4(addr, b[ntp]);
            }
#pragma unroll
            for (int mt = 0; mt < 4; mt++) {
#pragma unroll
                for (int nt = 0; nt < 4; nt++) {
                    uint32_t b0 = b[nt >> 1][(nt & 1) * 2];
                    uint32_t b1 = b[nt >> 1][(nt & 1) * 2 + 1];
                    mma_f16(acc[mt * 4 + nt], a[mt], b0, b1);
                }
            }
        }
        stage = (stage + 1 == NSTAGE) ? 0 : stage + 1;
    }

    // ---- epilogue ----
    __half* out16 = (__half*)outv;
    float*  outf  = (float*)outv;
#pragma unroll
    for (int mt = 0; mt < 4; mt++) {
        int rl0 = warpM * 64 + mt * 16 + g;
        int r0 = tileStart + rl0;
        int r1 = r0 + 8;
        int tok0 = 0, tok1 = 0; float w0 = 0.f, w1 = 0.f;
        if (EPI == 2) {
            tok0 = g_rowtok[r0]; tok1 = g_rowtok[r1];
            w0 = g_roww[r0];     w1 = g_roww[r1];
        }
#pragma unroll
        for (int nt = 0; nt < 4; nt++) {
            float* c = acc[mt * 4 + nt];
            int colL = warpN * 32 + nt * 8 + 2 * t;
            int col = nbase + colL;
            if (EPI == 0) {
                float b0 = par_b[colL], b1 = par_b[colL + 1];
                float s0 = par_sc[colL], s1 = par_sc[colL + 1];
                float h0 = par_sh[colL], h1 = par_sh[colL + 1];
                __half2 o0 = __floats2half2_rn(
                    fmaf(fmaxf(c[0] + b0, 0.f), s0, h0),
                    fmaf(fmaxf(c[1] + b1, 0.f), s1, h1));
                __half2 o1 = __floats2half2_rn(
                    fmaf(fmaxf(c[2] + b0, 0.f), s0, h0),
                    fmaf(fmaxf(c[3] + b1, 0.f), s1, h1));
                *(__half2*)(out16 + (size_t)r0 * Hout + col) = o0;
                *(__half2*)(out16 + (size_t)r1 * Hout + col) = o1;
            } else if (EPI == 1) {
                float b0 = par_b[colL], b1 = par_b[colL + 1];
                float2 o0, o1;
                o0.x = 1.f / (1.f + __expf(-(c[0] + b0)));
                o0.y = 1.f / (1.f + __expf(-(c[1] + b1)));
                o1.x = 1.f / (1.f + __expf(-(c[2] + b0)));
                o1.y = 1.f / (1.f + __expf(-(c[3] + b1)));
                *(float2*)(outf + (size_t)r0 * Hout + col) = o0;
                *(float2*)(outf + (size_t)r1 * Hout + col) = o1;
            } else {
                float b0 = par_b[colL], b1 = par_b[colL + 1];
                if (tok0 >= 0) {
                    float* orow = outf + (size_t)tok0 * Hout + col;
                    atomicAdd(&orow[0], w0 * (1.f / (1.f + __expf(-(c[0] + b0)))));
                    atomicAdd(&orow[1], w0 * (1.f / (1.f + __expf(-(c[1] + b1)))));
                }
                if (tok1 >= 0) {
                    float* orow = outf + (size_t)tok1 * Hout + col;
                    atomicAdd(&orow[0], w1 * (1.f / (1.f + __expf(-(c[2] + b0)))));
                    atomicAdd(&orow[1], w1 * (1.f / (1.f + __expf(-(c[3] + b1)))));
                }
            }
        }
    }
}

// ---------------- launch ----------------
extern "C" void kernel_launch(void* const* d_in, const int* in_sizes, int n_in,
                              void* d_out, int out_size) {
    (void)in_sizes; (void)n_in; (void)out_size;

    const float* x   = (const float*)d_in[0];
    const float* Wg  = (const float*)d_in[1];
    const float* W1  = (const float*)d_in[2];
    const float* b1  = (const float*)d_in[3];
    const float* g1  = (const float*)d_in[4];
    const float* be1 = (const float*)d_in[5];
    const float* m1  = (const float*)d_in[6];
    const float* v1  = (const float*)d_in[7];
    const float* W2  = (const float*)d_in[8];
    const float* b2  = (const float*)d_in[9];
    const float* g2  = (const float*)d_in[10];
    const float* be2 = (const float*)d_in[11];
    const float* m2  = (const float*)d_in[12];
    const float* v2  = (const float*)d_in[13];
    const float* W3  = (const float*)d_in[14];
    const float* b3  = (const float*)d_in[15];
    const float* sW1 = (const float*)d_in[16];
    const float* sb1 = (const float*)d_in[17];
    const float* sg1 = (const float*)d_in[18];
    const float* sbe1= (const float*)d_in[19];
    const float* sm1 = (const float*)d_in[20];
    const float* sv1 = (const float*)d_in[21];
    const float* sW2 = (const float*)d_in[22];
    const float* sb2 = (const float*)d_in[23];
    const float* sg2 = (const float*)d_in[24];
    const float* sbe2= (const float*)d_in[25];
    const float* sm2 = (const float*)d_in[26];
    const float* sv2 = (const float*)d_in[27];
    const float* sW3 = (const float*)d_in[28];
    const float* sb3 = (const float*)d_in[29];
    float* out = (float*)d_out;

    __half *x16, *w1h, *w2h, *w3h, *sw1h, *sw2h, *sw3h, *bufA, *bufB;
    int* off;
    cudaGetSymbolAddress((void**)&x16,  g_x16);
    cudaGetSymbolAddress((void**)&w1h,  g_w1);
    cudaGetSymbolAddress((void**)&w2h,  g_w2);
    cudaGetSymbolAddress((void**)&w3h,  g_w3);
    cudaGetSymbolAddress((void**)&sw1h, g_sw1);
    cudaGetSymbolAddress((void**)&sw2h, g_sw2);
    cudaGetSymbolAddress((void**)&sw3h, g_sw3);
    cudaGetSymbolAddress((void**)&bufA, g_bufA);
    cudaGetSymbolAddress((void**)&bufB, g_bufB);
    cudaGetSymbolAddress((void**)&off,  g_off);

    cudaFuncSetAttribute(gemm_h<0, true>,  cudaFuncAttributeMaxDynamicSharedMemorySize, SMEM_BYTES);
    cudaFuncSetAttribute(gemm_h<0, false>, cudaFuncAttributeMaxDynamicSharedMemorySize, SMEM_BYTES);
    cudaFuncSetAttribute(gemm_h<1, false>, cudaFuncAttributeMaxDynamicSharedMemorySize, SMEM_BYTES);
    cudaFuncSetAttribute(gemm_h<2, false>, cudaFuncAttributeMaxDynamicSharedMemorySize, SMEM_BYTES);

    // routing
    k_init<<<(ROWS_MAX + 255) / 256, 256>>>();
    k_gate<<<N_TOK / 8, 256>>>(x, Wg);
    k_offsets<<<1, 32>>>();
    k_scatter<<<(N_TOK + 255) / 256, 256>>>();

    // fp32 -> fp16 conversions
    {
        struct { const float* s; __half* d; int n; } cv[7] = {
            { x,   x16,  N_TOK * DIM },
            { W1,  w1h,  NEXP * HID * DIM },
            { W2,  w2h,  NEXP * HID * HID },
            { W3,  w3h,  NEXP * OUTD * HID },
            { sW1, sw1h, HID * DIM },
            { sW2, sw2h, HID * HID },
            { sW3, sw3h, OUTD * HID },
        };
        for (int i = 0; i < 7; i++)
            k_cvt<<<(cv[i].n / 4 + 255) / 256, 256>>>(cv[i].s, cv[i].d, cv[i].n);
    }

    // shared expert: x16 -> bufA -> bufB -> out (plain store initializes d_out)
    gemm_h<0, false><<<dim3(HID / BN, N_TOK / BM), 256, SMEM_BYTES>>>(
        x16, sw1h, sb1, sg1, sbe1, sm1, sv1, bufA, DIM, HID, 0, 0, nullptr);
    gemm_h<0, false><<<dim3(HID / BN, N_TOK / BM), 256, SMEM_BYTES>>>(
        bufA, sw2h, sb2, sg2, sbe2, sm2, sv2, bufB, HID, HID, 0, 0, nullptr);
    gemm_h<1, false><<<dim3(OUTD / BN, N_TOK / BM), 256, SMEM_BYTES>>>(
        bufB, sw3h, sb3, nullptr, nullptr, nullptr, nullptr, out, HID, OUTD, 0, 0, nullptr);

    // routed experts (top-2 compacted): gather -> bufA -> bufB -> out (+=)
    gemm_h<0, true><<<dim3(HID / BN, ROWS_MAX / BM), 256, SMEM_BYTES>>>(
        x16, w1h, b1, g1, be1, m1, v1, bufA, DIM, HID, (long)HID * DIM, HID, off);
    gemm_h<0, false><<<dim3(HID / BN, ROWS_MAX / BM), 256, SMEM_BYTES>>>(
        bufA, w2h, b2, g2, be2, m2, v2, bufB, HID, HID, (long)HID * HID, HID, off);
    gemm_h<2, false><<<dim3(OUTD / BN, ROWS_MAX / BM), 256, SMEM_BYTES>>>(
        bufB, w3h, b3, nullptr, nullptr, nullptr, nullptr, out, HID, OUTD, (long)OUTD * HID, OUTD, off);
}